// round 12
// baseline (speedup 1.0000x reference)
#include <cuda_runtime.h>

// GRU persistent v6: 512 threads, 4 independent quarter-pipelines (8 rows x
// 4-warp k-split each), per-quarter named barriers + 16-CTA group barriers.
#define SEQLEN 512
#define HPADF  260
#define XPADF  132
#define WT4    1536
#define QBLK   6240

__device__ float    g_h [256 * 256];
__device__ float    g_rh[256 * 256];
__device__ unsigned g_count[32 * 32];
__device__ unsigned g_sense[32 * 32];

__device__ __forceinline__ void ffma2(unsigned long long &a,
                                      unsigned long long x, unsigned long long y) {
    asm("fma.rn.f32x2 %0, %1, %2, %0;" : "+l"(a) : "l"(x), "l"(y));
}
__device__ __forceinline__ float f2sum(unsigned long long v) {
    return __uint_as_float((unsigned)v) + __uint_as_float((unsigned)(v >> 32));
}
__device__ __forceinline__ float sig_(float a) { return 1.0f / (1.0f + __expf(-a)); }
__device__ __forceinline__ float tanh_(float a) { return 2.0f / (1.0f + __expf(-2.0f * a)) - 1.0f; }
__device__ __forceinline__ void barn(int id) {
    asm volatile("bar.sync %0, 128;" :: "r"(id) : "memory");
}
__device__ __forceinline__ void grp_arrive(unsigned &sense, unsigned *cnt,
                                           unsigned *sns, int nb, int lt) {
    barn(nb);
    if (lt == 0) {
        sense ^= 1u;
        __threadfence();
        if (atomicAdd(cnt, 1u) == 15u) {
            atomicExch(cnt, 0u);
            __threadfence();
            atomicExch(sns, sense);
        }
    }
}
__device__ __forceinline__ void grp_wait(unsigned sense, unsigned *sns, int nb, int lt) {
    if (lt == 0) {
        while (*((volatile unsigned *)sns) != sense) { }
        __threadfence();
    }
    barn(nb);
}

#define ACC2(a, wv, hv) { ffma2(a, (wv).x, (hv).x); ffma2(a, (wv).y, (hv).y); }
#define ZR8(v0,v1,z0,z1,r0,r1) \
    ACC2(az[0],z0,v0); ACC2(az[1],z1,v0); ACC2(az[2],z0,v1); ACC2(az[3],z1,v1); \
    ACC2(ar[0],r0,v0); ACC2(ar[1],r1,v0); ACC2(ar[2],r0,v1); ACC2(ar[3],r1,v1);
#define C4(v0,v1,c0,c1) \
    ACC2(ac[0],c0,v0); ACC2(ac[1],c1,v0); ACC2(ac[2],c0,v1); ACC2(ac[3],c1,v1);

__global__ void __launch_bounds__(512, 1)
gru_persistent(const float* __restrict__ X,
               const float* __restrict__ Wz, const float* __restrict__ bz,
               const float* __restrict__ Wr, const float* __restrict__ br,
               const float* __restrict__ Wc, const float* __restrict__ bc,
               float* __restrict__ out)
{
    extern __shared__ float sm[];
    float* wT = sm;                       // 18432 floats, k-major interleaved
    float* sB = sm + 18432;               // 48
    const int tid = threadIdx.x;
    const int q  = tid >> 7, lt = tid & 127;
    const int w  = lt >> 5, l = lt & 31, rr = l & 3, cc = l >> 2;
    const int bt = blockIdx.x & 7, hsb = blockIdx.x >> 3;
    const int bbase = bt * 32 + q * 8, jbase = hsb * 16;
    const int nb = 1 + q;
    float* hb   = sm + 18480 + q * QBLK;
    float* h_s  = hb;                     // 8 x 260 = 2080
    float* rh_s = hb + 2080;              // 8 x 260
    float* x_s  = hb + 4160;              // 8 x 132 = 1056
    float* red  = hb + 5216;              // 1024

    unsigned* cnt = &g_count[(bt * 4 + q) * 32];
    unsigned* sns = &g_sense[(bt * 4 + q) * 32];
    unsigned sense = 0;
    if (lt == 0) sense = *((volatile unsigned *)sns);

    {   // weights: k-major, col pairs interleaved (slot = (c>>1) + 8*(c&1))
        float4* wp = (float4*)wT;
        for (int idx = tid; idx < 3 * WT4; idx += 512) {
            int g = idx / WT4, rem = idx % WT4, k4 = rem >> 4, c = rem & 15;
            const float4* W4 = (const float4*)((g == 0) ? Wz : (g == 1) ? Wr : Wc);
            wp[(g * 96 + k4) * 16 + ((c >> 1) + 8 * (c & 1))] = W4[(jbase + c) * 96 + k4];
        }
        if (tid < 16) {
            sB[tid] = bz[jbase + tid]; sB[16 + tid] = br[jbase + tid];
            sB[32 + tid] = bc[jbase + tid];
        }
    }
    for (int i = lt; i < 8 * HPADF; i += 128) h_s[i] = 0.0f;
    #pragma unroll
    for (int j = 0; j < 2; j++) {        // x tile for t=0: 8 rows x 32 f4
        int idx = lt + 128 * j, row = idx >> 5, c4 = idx & 31;
        *(float4*)(x_s + row * XPADF + c4 * 4) =
            ((const float4*)X)[(size_t)(bbase + row) * (SEQLEN * 32) + c4];
    }
    __syncthreads();

    const ulonglong2* hA = (const ulonglong2*)(h_s + rr * HPADF);
    const ulonglong2* hB = (const ulonglong2*)(h_s + (rr + 4) * HPADF);
    const ulonglong2* rA = (const ulonglong2*)(rh_s + rr * HPADF);
    const ulonglong2* rB = (const ulonglong2*)(rh_s + (rr + 4) * HPADF);
    const ulonglong2* xA = (const ulonglong2*)(x_s + rr * XPADF);
    const ulonglong2* xB = (const ulonglong2*)(x_s + (rr + 4) * XPADF);
    const ulonglong2* wzp = (const ulonglong2*)wT + cc;
    const ulonglong2* wrp = wzp + WT4;
    const ulonglong2* wcp = wzp + 2 * WT4;
    const int kw = w * 16, kx = w * 8, sw = w ^ rr;
    const int orow = lt >> 4, ocol = lt & 15;
    const float bzv = sB[ocol], brv = sB[16 + ocol], bcv = sB[32 + ocol];

    unsigned long long az[4], ar[4], ac[4];
    #pragma unroll
    for (int i = 0; i < 4; i++) { az[i] = 0; ar[i] = 0; }
    #pragma unroll 4
    for (int kk = 0; kk < 8; kk++) {            // z/r x-part, t=0
        int k4 = 64 + kx + kk, kq = kx + kk;
        ulonglong2 v0 = xA[kq], v1 = xB[kq];
        ulonglong2 z0 = wzp[k4*16], z1 = wzp[k4*16+8];
        ulonglong2 r0 = wrp[k4*16], r1 = wrp[k4*16+8];
        ZR8(v0,v1,z0,z1,r0,r1)
    }

    // anti-phase stagger: quarter q runs 4*q dummy phase1 h-passes.
    // h_s is all zeros -> adds exactly 0 (numeric identity) but offsets the
    // four pipelines ~quarter-step apart so their stall windows interleave.
    #pragma unroll 1
    for (int d = 0; d < 4 * q; d++) {
        #pragma unroll 4
        for (int kk = 0; kk < 16; kk++) {
            int k4 = kw + kk;
            ulonglong2 v0 = hA[k4], v1 = hB[k4];
            ulonglong2 z0 = wzp[k4*16], z1 = wzp[k4*16+8];
            ulonglong2 r0 = wrp[k4*16], r1 = wrp[k4*16+8];
            ZR8(v0,v1,z0,z1,r0,r1)
        }
    }

    for (int t = 0; t < SEQLEN; t++) {
        #pragma unroll 4
        for (int kk = 0; kk < 16; kk++) {       // phase1 h-part
            int k4 = kw + kk;
            ulonglong2 v0 = hA[k4], v1 = hB[k4];
            ulonglong2 z0 = wzp[k4*16], z1 = wzp[k4*16+8];
            ulonglong2 r0 = wrp[k4*16], r1 = wrp[k4*16+8];
            ZR8(v0,v1,z0,z1,r0,r1)
        }
        #pragma unroll
        for (int i = 0; i < 2; i++)
            #pragma unroll
            for (int e = 0; e < 2; e++) {
                int o = (rr + 4*i) * 16 + 2*cc + e;
                red[(o << 2) + sw]         = f2sum(az[i*2+e]);
                red[((128 + o) << 2) + sw] = f2sum(ar[i*2+e]);
            }
        barn(nb);
        float4 p0 = *(float4*)(red + lt*4);
        float4 p1 = *(float4*)(red + (128 + lt)*4);
        float zz = sig_(p0.x+p0.y+p0.z+p0.w + bzv);
        float rv = sig_(p1.x+p1.y+p1.z+p1.w + brv);
        float h_o = h_s[orow * HPADF + jbase + ocol];
        g_rh[(bbase + orow) * 256 + jbase + ocol] = rv * h_o;

        grp_arrive(sense, cnt, sns, nb, lt);        // A arrive
        #pragma unroll
        for (int i = 0; i < 4; i++) ac[i] = 0;
        #pragma unroll 4
        for (int kk = 0; kk < 8; kk++) {            // cand x-part (overlap A)
            int k4 = 64 + kx + kk, kq = kx + kk;
            ulonglong2 v0 = xA[kq], v1 = xB[kq];
            ulonglong2 c0 = wcp[k4*16], c1 = wcp[k4*16+8];
            C4(v0,v1,c0,c1)
        }
        grp_wait(sense, sns, nb, lt);               // A wait

        {   // rh gather: stage 4 LDGs (MLP=4), then 4 STS
            float4 tmp[4];
            #pragma unroll
            for (int j = 0; j < 4; j++) {
                int idx = lt + 128*j;
                tmp[j] = ((const float4*)g_rh)[(bbase + (idx >> 6)) * 64 + (idx & 63)];
            }
            #pragma unroll
            for (int j = 0; j < 4; j++) {
                int idx = lt + 128*j;
                *(float4*)(rh_s + (idx >> 6) * HPADF + (idx & 63) * 4) = tmp[j];
            }
        }
        barn(nb);

        #pragma unroll 4
        for (int kk = 0; kk < 16; kk++) {           // phase2 h-part
            int k4 = kw + kk;
            ulonglong2 v0 = rA[k4], v1 = rB[k4];
            ulonglong2 c0 = wcp[k4*16], c1 = wcp[k4*16+8];
            C4(v0,v1,c0,c1)
        }
        #pragma unroll
        for (int i = 0; i < 2; i++)
            #pragma unroll
            for (int e = 0; e < 2; e++) {
                int o = (rr + 4*i) * 16 + 2*cc + e;
                red[(o << 2) + sw] = f2sum(ac[i*2+e]);
            }
        barn(nb);
        float4 q0 = *(float4*)(red + lt*4);
        float cv = tanh_(q0.x+q0.y+q0.z+q0.w + bcv);
        float hn = h_o + zz * (cv - h_o);
        g_h[(bbase + orow) * 256 + jbase + ocol] = hn;

        grp_arrive(sense, cnt, sns, nb, lt);        // B arrive

        // overlap B: out store + x(t+1) prefetch + z/r x-part for t+1
        out[((size_t)t * 256 + bbase + orow) * 256 + jbase + ocol] = hn;
        #pragma unroll
        for (int i = 0; i < 4; i++) { az[i] = 0; ar[i] = 0; }
        if (t + 1 < SEQLEN) {
            float4 xt[2];
            #pragma unroll
            for (int j = 0; j < 2; j++) {
                int idx = lt + 128*j;
                xt[j] = ((const float4*)X)[(size_t)(bbase + (idx >> 5)) * (SEQLEN * 32)
                                           + (size_t)(t + 1) * 32 + (idx & 31)];
            }
            #pragma unroll
            for (int j = 0; j < 2; j++) {
                int idx = lt + 128*j;
                *(float4*)(x_s + (idx >> 5) * XPADF + (idx & 31) * 4) = xt[j];
            }
            barn(nb);
            #pragma unroll 4
            for (int kk = 0; kk < 8; kk++) {
                int k4 = 64 + kx + kk, kq = kx + kk;
                ulonglong2 v0 = xA[kq], v1 = xB[kq];
                ulonglong2 z0 = wzp[k4*16], z1 = wzp[k4*16+8];
                ulonglong2 r0 = wrp[k4*16], r1 = wrp[k4*16+8];
                ZR8(v0,v1,z0,z1,r0,r1)
            }
        }
        grp_wait(sense, sns, nb, lt);               // B wait
        if (t + 1 < SEQLEN) {
            float4 tmp[4];
            #pragma unroll
            for (int j = 0; j < 4; j++) {           // h gather (staged)
                int idx = lt + 128*j;
                tmp[j] = ((const float4*)g_h)[(bbase + (idx >> 6)) * 64 + (idx & 63)];
            }
            #pragma unroll
            for (int j = 0; j < 4; j++) {
                int idx = lt + 128*j;
                *(float4*)(h_s + (idx >> 6) * HPADF + (idx & 63) * 4) = tmp[j];
            }
            barn(nb);
        }
    }
}

extern "C" void kernel_launch(void* const* d_in, const int* in_sizes, int n_in,
                              void* d_out, int out_size) {
    const float* X  = (const float*)d_in[0];
    const float* Wz = (const float*)d_in[1];
    const float* bz = (const float*)d_in[2];
    const float* Wr = (const float*)d_in[3];
    const float* br = (const float*)d_in[4];
    const float* Wc = (const float*)d_in[5];
    const float* bc = (const float*)d_in[6];
    float* out = (float*)d_out;

    int smem_bytes = (18480 + 4 * QBLK) * (int)sizeof(float);   // 173,760 B
    cudaFuncSetAttribute(gru_persistent,
                         cudaFuncAttributeMaxDynamicSharedMemorySize, smem_bytes);
    gru_persistent<<<128, 512, smem_bytes>>>(X, Wz, bz, Wr, br, Wc, bc, out);
}